// round 7
// baseline (speedup 1.0000x reference)
#include <cuda_runtime.h>
#include <cuda_bf16.h>

typedef unsigned long long ull;

#define Bn   512
#define Tn   256
#define Hn   256
#define HORn 22
#define BT   4
#define NK2  128          // Hn/2 k-pairs
#define KS   70           // k2 rows cached in SMEM (per matrix)
#define NTHR 256
#define NCTA (Bn/BT)      // 128

// SMEM layout (bytes):
//   uz_sm  : KS*256 words   (KS*1024)
//   ur_sm  : KS*1024
//   uh_sm  : KS*1024
//   hp     : 128 k2 * 4 rows * 8B  = 4096   (paired h)
//   rhp    : 4096                            (paired r*h)
//   eps    : 256 t * 4 rows * 4B   = 4096
#define SMEM_BYTES (3*KS*1024 + 3*4096)   // 227328 <= 232448 max dynamic

// Packed bf16x2 U weights: [mat(z,r,h)][k2][j], word = bf16(u[2k2][j]) | bf16(u[2k2+1][j])<<16
__device__ unsigned g_upk[3 * NK2 * Hn];

__global__ void ggru_pack_kernel(const float* __restrict__ Uz,
                                 const float* __restrict__ Ur,
                                 const float* __restrict__ Uh) {
    int idx = blockIdx.x * blockDim.x + threadIdx.x;
    if (idx >= 3 * NK2 * Hn) return;
    int m   = idx >> 15;          // / 32768
    int rem = idx & 32767;
    int k2  = rem >> 8;
    int j   = rem & 255;
    const float* U = (m == 0) ? Uz : ((m == 1) ? Ur : Uh);
    float a = U[(2 * k2) * Hn + j];
    float b = U[(2 * k2 + 1) * Hn + j];
    unsigned lo = (unsigned)__bfloat16_as_ushort(__float2bfloat16(a));
    unsigned hi = (unsigned)__bfloat16_as_ushort(__float2bfloat16(b));
    g_upk[idx] = lo | (hi << 16);
}

// ---- f32x2 helpers (Blackwell packed math; PTX-only) ----
static __device__ __forceinline__ ull bfpair(unsigned w) {
    // bf16x2 word (lo=even k, hi=odd k) -> packed f32x2 (even, odd)
    unsigned lo = w << 16;
    unsigned hi = w & 0xFFFF0000u;
    ull p;
    asm("mov.b64 %0, {%1, %2};" : "=l"(p) : "r"(lo), "r"(hi));
    return p;
}
static __device__ __forceinline__ ull fma2(ull a, ull b, ull c) {
    ull d;
    asm("fma.rn.f32x2 %0, %1, %2, %3;" : "=l"(d) : "l"(a), "l"(b), "l"(c));
    return d;
}
static __device__ __forceinline__ float red2(ull a) {
    unsigned lo, hi;
    asm("mov.b64 {%0, %1}, %2;" : "=r"(lo), "=r"(hi) : "l"(a));
    return __uint_as_float(lo) + __uint_as_float(hi);
}

static __device__ __forceinline__ float sigf(float x) {
    return __fdividef(1.0f, 1.0f + __expf(-x));
}
static __device__ __forceinline__ float tanhf_fast(float x) {
    float e = __expf(2.0f * x);
    return 1.0f - __fdividef(2.0f, e + 1.0f);
}

__global__ void __launch_bounds__(NTHR, 1)
ggru_main_kernel(const float* __restrict__ x,
                 const float* __restrict__ Wzw, const float* __restrict__ Wzb,
                 const float* __restrict__ Uzb,
                 const float* __restrict__ Wrw, const float* __restrict__ Wrb,
                 const float* __restrict__ Urb,
                 const float* __restrict__ Whw, const float* __restrict__ Whb,
                 const float* __restrict__ Uhb,
                 const float* __restrict__ Wgw, const float* __restrict__ Wgb,
                 const float* __restrict__ p_om, const float* __restrict__ p_al,
                 const float* __restrict__ p_be, const float* __restrict__ p_ga,
                 const float* __restrict__ fc1w, const float* __restrict__ fc1b,
                 const float* __restrict__ fc2w, const float* __restrict__ fc2b,
                 float* __restrict__ out) {
    extern __shared__ unsigned char smem[];
    unsigned* uz_sm = (unsigned*)smem;            // [KS*256]
    unsigned* ur_sm = uz_sm + KS * 256;
    unsigned* uh_sm = ur_sm + KS * 256;
    float* hp     = (float*)(uh_sm + KS * 256);   // paired: hp[k2*8 + row*2 + comp]
    float* rhp    = hp + 1024;
    float* eps_sm = rhp + 1024;                   // [t*4 + row]

    const int j  = threadIdx.x;
    const int r0 = blockIdx.x * BT;

    // ---- prologue: fill SMEM ----
    for (int i = j; i < KS * 256; i += NTHR) {
        uz_sm[i] = g_upk[i];
        ur_sm[i] = g_upk[32768 + i];
        uh_sm[i] = g_upk[65536 + i];
    }
    for (int i = j; i < Tn * BT; i += NTHR) {
        int t = i >> 2, r = i & 3;
        eps_sm[i] = x[(r0 + r) * Tn + t];
    }
    for (int i = j; i < 1024; i += NTHR) hp[i] = 0.0f;

    // per-column weights in registers
    const float wzw = Wzw[j], wzb = Wzb[j], uzb = Uzb[j];
    const float wrw = Wrw[j], wrb = Wrb[j], urb = Urb[j];
    const float whw = Whw[j], whb = Whb[j], uhb = Uhb[j];
    const float wgw = Wgw[j], wgb = Wgb[j];

    // scalar params (computed redundantly per thread; precise path, one time)
    float om_raw = p_om[0];
    float omega  = ((om_raw > 20.0f) ? om_raw : log1pf(expf(om_raw))) + 1e-6f;
    float aP     = 1.0f / (1.0f + expf(-p_al[0]));
    float bP     = (1.0f / (1.0f + expf(-p_be[0]))) * (1.0f - aP * 0.99f);
    float gam    = p_ga[0];

    float h_reg[BT] = {0.f, 0.f, 0.f, 0.f};
    float epsq[BT]  = {1e-6f, 1e-6f, 1e-6f, 1e-6f};
    float sigq[BT]  = {1e-6f, 1e-6f, 1e-6f, 1e-6f};
    const int pbase = (j >> 1) * 8 + (j & 1);   // float index for paired h writes

    __syncthreads();

    const unsigned* pz_s = uz_sm + j;
    const unsigned* pr_s = ur_sm + j;
    const unsigned* ph_s = uh_sm + j;
    const unsigned* pz_g = g_upk + j;
    const unsigned* pr_g = g_upk + 32768 + j;
    const unsigned* ph_g = g_upk + 65536 + j;

    for (int t = 0; t < Tn; t++) {
        const float4 e4 = *(const float4*)(eps_sm + t * 4);
        float ev[BT] = {e4.x, e4.y, e4.z, e4.w};
        float gin[BT];
#pragma unroll
        for (int r = 0; r < BT; r++) {
            gin[r]  = omega + aP * epsq[r] + bP * sigq[r];
            epsq[r] = ev[r] * ev[r];
            sigq[r] = gin[r];
        }

        // ---- phase 1: z and r matvecs over previous h ----
        ull az[BT] = {0, 0, 0, 0};
        ull ar[BT] = {0, 0, 0, 0};
        {
            const ull* hpp = (const ull*)hp;
#pragma unroll 4
            for (int k2 = 0; k2 < KS; k2++) {
                ull upz = bfpair(pz_s[k2 * 256]);
                ull upr = bfpair(pr_s[k2 * 256]);
                ulonglong2 hA = *(const ulonglong2*)(hpp + k2 * 4);
                ulonglong2 hB = *(const ulonglong2*)(hpp + k2 * 4 + 2);
                az[0] = fma2(upz, hA.x, az[0]);
                az[1] = fma2(upz, hA.y, az[1]);
                az[2] = fma2(upz, hB.x, az[2]);
                az[3] = fma2(upz, hB.y, az[3]);
                ar[0] = fma2(upr, hA.x, ar[0]);
                ar[1] = fma2(upr, hA.y, ar[1]);
                ar[2] = fma2(upr, hB.x, ar[2]);
                ar[3] = fma2(upr, hB.y, ar[3]);
            }
#pragma unroll 4
            for (int k2 = KS; k2 < NK2; k2++) {
                ull upz = bfpair(pz_g[k2 * 256]);
                ull upr = bfpair(pr_g[k2 * 256]);
                ulonglong2 hA = *(const ulonglong2*)(hpp + k2 * 4);
                ulonglong2 hB = *(const ulonglong2*)(hpp + k2 * 4 + 2);
                az[0] = fma2(upz, hA.x, az[0]);
                az[1] = fma2(upz, hA.y, az[1]);
                az[2] = fma2(upz, hB.x, az[2]);
                az[3] = fma2(upz, hB.y, az[3]);
                ar[0] = fma2(upr, hA.x, ar[0]);
                ar[1] = fma2(upr, hA.y, ar[1]);
                ar[2] = fma2(upr, hB.x, ar[2]);
                ar[3] = fma2(upr, hB.y, ar[3]);
            }
        }
        float zz[BT];
#pragma unroll
        for (int r = 0; r < BT; r++) {
            float z  = sigf(red2(az[r]) + fmaf(ev[r], wzw, wzb) + uzb);
            float rg = sigf(red2(ar[r]) + fmaf(ev[r], wrw, wrb) + urb);
            zz[r] = z;
            rhp[pbase + r * 2] = rg * h_reg[r];   // paired layout for phase 2
        }
        __syncthreads();

        // ---- phase 2: h_tilde matvec over (r*h) ----
        ull ah[BT] = {0, 0, 0, 0};
        {
            const ull* rpp = (const ull*)rhp;
#pragma unroll 4
            for (int k2 = 0; k2 < KS; k2++) {
                ull uph = bfpair(ph_s[k2 * 256]);
                ulonglong2 hA = *(const ulonglong2*)(rpp + k2 * 4);
                ulonglong2 hB = *(const ulonglong2*)(rpp + k2 * 4 + 2);
                ah[0] = fma2(uph, hA.x, ah[0]);
                ah[1] = fma2(uph, hA.y, ah[1]);
                ah[2] = fma2(uph, hB.x, ah[2]);
                ah[3] = fma2(uph, hB.y, ah[3]);
            }
#pragma unroll 4
            for (int k2 = KS; k2 < NK2; k2++) {
                ull uph = bfpair(ph_g[k2 * 256]);
                ulonglong2 hA = *(const ulonglong2*)(rpp + k2 * 4);
                ulonglong2 hB = *(const ulonglong2*)(rpp + k2 * 4 + 2);
                ah[0] = fma2(uph, hA.x, ah[0]);
                ah[1] = fma2(uph, hA.y, ah[1]);
                ah[2] = fma2(uph, hB.x, ah[2]);
                ah[3] = fma2(uph, hB.y, ah[3]);
            }
        }
#pragma unroll
        for (int r = 0; r < BT; r++) {
            float ht = tanhf_fast(red2(ah[r]) + fmaf(ev[r], whw, whb) + uhb);
            float hh = (1.0f - zz[r]) * ht + zz[r] * h_reg[r];
            float gt = fmaf(gin[r], wgw, wgb);
            float hn = tanhf_fast(fmaf(gam, gt, hh));
            h_reg[r] = hn;
            hp[pbase + r * 2] = hn;
        }
        __syncthreads();
    }

    // ---- epilogue: fc1 -> relu -> fc2 -> softplus -> vol ----
    float* h_lin = (float*)smem;          // reuse uz_sm region: [4][256]
    float* hid   = h_lin + BT * Hn;       // [4][256]
#pragma unroll
    for (int r = 0; r < BT; r++) h_lin[r * Hn + j] = h_reg[r];
    __syncthreads();

    float acc[BT] = {0.f, 0.f, 0.f, 0.f};
    for (int k = 0; k < Hn; k++) {
        float f = fc1w[k * Hn + j];
#pragma unroll
        for (int r = 0; r < BT; r++) acc[r] = fmaf(h_lin[r * Hn + k], f, acc[r]);
    }
    float b1 = fc1b[j];
#pragma unroll
    for (int r = 0; r < BT; r++) hid[r * Hn + j] = fmaxf(acc[r] + b1, 0.0f);
    __syncthreads();

    if (j < BT * HORn) {                  // 88 threads
        int r = j / HORn;
        int o = j - r * HORn;
        float s = 0.0f;
        for (int k = 0; k < Hn; k++) s = fmaf(hid[r * Hn + k], fc2w[k * HORn + o], s);
        s += fc2b[o];
        float nn = (s > 20.0f) ? s : log1pf(expf(s));
        float vb = sqrtf(sigq[r] + 1e-8f);
        float vol = vb * (1.0f + nn);
        vol = fminf(fmaxf(vol, 0.01f), 10.0f);
        out[(r0 + r) * HORn + o] = vol;
    }
    if (j >= BT * HORn && j < BT * HORn + BT) {   // 4 threads write sigma_sq
        int r = j - BT * HORn;
        out[Bn * HORn + r0 + r] = sigq[r];
    }
}

extern "C" void kernel_launch(void* const* d_in, const int* in_sizes, int n_in,
                              void* d_out, int out_size) {
    const float* x    = (const float*)d_in[0];
    const float* Wzw  = (const float*)d_in[1];
    const float* Wzb  = (const float*)d_in[2];
    const float* Uzw  = (const float*)d_in[3];
    const float* Uzb  = (const float*)d_in[4];
    const float* Wrw  = (const float*)d_in[5];
    const float* Wrb  = (const float*)d_in[6];
    const float* Urw  = (const float*)d_in[7];
    const float* Urb  = (const float*)d_in[8];
    const float* Whw  = (const float*)d_in[9];
    const float* Whb  = (const float*)d_in[10];
    const float* Uhw  = (const float*)d_in[11];
    const float* Uhb  = (const float*)d_in[12];
    const float* Wgw  = (const float*)d_in[13];
    const float* Wgb  = (const float*)d_in[14];
    const float* om   = (const float*)d_in[15];
    const float* al   = (const float*)d_in[16];
    const float* be   = (const float*)d_in[17];
    const float* ga   = (const float*)d_in[18];
    const float* fc1w = (const float*)d_in[19];
    const float* fc1b = (const float*)d_in[20];
    const float* fc2w = (const float*)d_in[21];
    const float* fc2b = (const float*)d_in[22];
    float* out = (float*)d_out;

    ggru_pack_kernel<<<(3 * NK2 * Hn + 255) / 256, 256>>>(Uzw, Urw, Uhw);

    cudaFuncSetAttribute(ggru_main_kernel,
                         cudaFuncAttributeMaxDynamicSharedMemorySize, SMEM_BYTES);
    ggru_main_kernel<<<NCTA, NTHR, SMEM_BYTES>>>(
        x, Wzw, Wzb, Uzb, Wrw, Wrb, Urb, Whw, Whb, Uhb,
        Wgw, Wgb, om, al, be, ga, fc1w, fc1b, fc2w, fc2b, out);
}

// round 8
// speedup vs baseline: 1.2956x; 1.2956x over previous
#include <cuda_runtime.h>
#include <cuda_bf16.h>

typedef unsigned long long ull;

#define Bn   512
#define Tn   256
#define Hn   256
#define HORn 22
#define BT   4
#define NK2  128          // Hn/2 k-pairs
#define KS   64           // k2 rows cached in SMEM (per matrix) == g=0's half
#define NTHR 512
#define NCTA (Bn/BT)      // 128

// SMEM layout (bytes):
//   uz_sm : 64*256 words = 65536
//   ur_sm : 65536
//   uh_sm : 65536
//   hp    : 4096  (paired h:  hp[k2*8 + row*2 + comp])
//   rhp   : 4096  (paired r*h)
//   eps   : 4096  ([t*4 + row])
//   part  : 8192  (partial-sum exchange: part[i*256 + j], i in [0,8))
#define SMEM_BYTES (3*65536 + 3*4096 + 8192)   // 217088

// Packed bf16x2 U weights: [mat(z,r,h)][k2][j], word = bf16(u[2k2][j]) | bf16(u[2k2+1][j])<<16
__device__ unsigned g_upk[3 * NK2 * Hn];

__global__ void ggru_pack_kernel(const float* __restrict__ Uz,
                                 const float* __restrict__ Ur,
                                 const float* __restrict__ Uh) {
    int idx = blockIdx.x * blockDim.x + threadIdx.x;
    if (idx >= 3 * NK2 * Hn) return;
    int m   = idx >> 15;
    int rem = idx & 32767;
    int k2  = rem >> 8;
    int j   = rem & 255;
    const float* U = (m == 0) ? Uz : ((m == 1) ? Ur : Uh);
    float a = U[(2 * k2) * Hn + j];
    float b = U[(2 * k2 + 1) * Hn + j];
    unsigned lo = (unsigned)__bfloat16_as_ushort(__float2bfloat16(a));
    unsigned hi = (unsigned)__bfloat16_as_ushort(__float2bfloat16(b));
    g_upk[idx] = lo | (hi << 16);
}

// ---- f32x2 helpers (Blackwell packed math; PTX-only) ----
static __device__ __forceinline__ ull bfpair(unsigned w) {
    unsigned lo = w << 16;
    unsigned hi = w & 0xFFFF0000u;
    ull p;
    asm("mov.b64 %0, {%1, %2};" : "=l"(p) : "r"(lo), "r"(hi));
    return p;
}
static __device__ __forceinline__ ull fma2(ull a, ull b, ull c) {
    ull d;
    asm("fma.rn.f32x2 %0, %1, %2, %3;" : "=l"(d) : "l"(a), "l"(b), "l"(c));
    return d;
}
static __device__ __forceinline__ float red2(ull a) {
    unsigned lo, hi;
    asm("mov.b64 {%0, %1}, %2;" : "=r"(lo), "=r"(hi) : "l"(a));
    return __uint_as_float(lo) + __uint_as_float(hi);
}

static __device__ __forceinline__ float sigf(float x) {
    return __fdividef(1.0f, 1.0f + __expf(-x));
}
static __device__ __forceinline__ float tanhf_fast(float x) {
    float e = __expf(2.0f * x);
    return 1.0f - __fdividef(2.0f, e + 1.0f);
}

__global__ void __launch_bounds__(NTHR, 1)
ggru_main_kernel(const float* __restrict__ x,
                 const float* __restrict__ Wzw, const float* __restrict__ Wzb,
                 const float* __restrict__ Uzb,
                 const float* __restrict__ Wrw, const float* __restrict__ Wrb,
                 const float* __restrict__ Urb,
                 const float* __restrict__ Whw, const float* __restrict__ Whb,
                 const float* __restrict__ Uhb,
                 const float* __restrict__ Wgw, const float* __restrict__ Wgb,
                 const float* __restrict__ p_om, const float* __restrict__ p_al,
                 const float* __restrict__ p_be, const float* __restrict__ p_ga,
                 const float* __restrict__ fc1w, const float* __restrict__ fc1b,
                 const float* __restrict__ fc2w, const float* __restrict__ fc2b,
                 float* __restrict__ out) {
    extern __shared__ unsigned char smem[];
    unsigned* uz_sm = (unsigned*)smem;            // [64*256]
    unsigned* ur_sm = uz_sm + KS * 256;
    unsigned* uh_sm = ur_sm + KS * 256;
    float* hp     = (float*)(uh_sm + KS * 256);
    float* rhp    = hp + 1024;
    float* eps_sm = rhp + 1024;
    float* part   = eps_sm + 1024;                // [8][256]

    const int tid = threadIdx.x;
    const int j   = tid & 255;        // output column
    const int g   = tid >> 8;         // k-half: 0 -> k2 [0,64) (SMEM), 1 -> [64,128) (L2)
    const int r0  = blockIdx.x * BT;

    // ---- prologue: fill SMEM ----
    for (int i = tid; i < KS * 256; i += NTHR) {
        uz_sm[i] = g_upk[i];
        ur_sm[i] = g_upk[32768 + i];
        uh_sm[i] = g_upk[65536 + i];
    }
    for (int i = tid; i < Tn * BT; i += NTHR) {
        int t = i >> 2, r = i & 3;
        eps_sm[i] = x[(r0 + r) * Tn + t];
    }
    for (int i = tid; i < 1024; i += NTHR) hp[i] = 0.0f;

    // per-column gate weights (only g=0 uses them, but load uniformly)
    const float wzw = Wzw[j], wzb = Wzb[j], uzb = Uzb[j];
    const float wrw = Wrw[j], wrb = Wrb[j], urb = Urb[j];
    const float whw = Whw[j], whb = Whb[j], uhb = Uhb[j];
    const float wgw = Wgw[j], wgb = Wgb[j];

    float om_raw = p_om[0];
    float omega  = ((om_raw > 20.0f) ? om_raw : log1pf(expf(om_raw))) + 1e-6f;
    float aP     = 1.0f / (1.0f + expf(-p_al[0]));
    float bP     = (1.0f / (1.0f + expf(-p_be[0]))) * (1.0f - aP * 0.99f);
    float gam    = p_ga[0];

    float h_reg[BT] = {0.f, 0.f, 0.f, 0.f};
    float epsq[BT]  = {1e-6f, 1e-6f, 1e-6f, 1e-6f};
    float sigq[BT]  = {1e-6f, 1e-6f, 1e-6f, 1e-6f};
    const int pbase = (j >> 1) * 8 + (j & 1);

    __syncthreads();

    // per-thread weight stream pointers (column j, this thread's k-half)
    const unsigned* pz = (g == 0) ? (uz_sm + j) : (g_upk + 64 * 256 + j);
    const unsigned* pr = (g == 0) ? (ur_sm + j) : (g_upk + 32768 + 64 * 256 + j);
    const unsigned* ph = (g == 0) ? (uh_sm + j) : (g_upk + 65536 + 64 * 256 + j);
    const ull* hpp  = (const ull*)hp  + g * 64 * 4;   // this half's h pairs
    const ull* rpp  = (const ull*)rhp + g * 64 * 4;

    for (int t = 0; t < Tn; t++) {
        const float4 e4 = *(const float4*)(eps_sm + t * 4);
        float ev[BT] = {e4.x, e4.y, e4.z, e4.w};
        float gin[BT];
#pragma unroll
        for (int r = 0; r < BT; r++) {
            gin[r]  = omega + aP * epsq[r] + bP * sigq[r];
            epsq[r] = ev[r] * ev[r];
            sigq[r] = gin[r];
        }

        // ---- phase 1: z and r partial matvecs over previous h (this k-half) ----
        ull az[BT] = {0, 0, 0, 0};
        ull ar[BT] = {0, 0, 0, 0};
#pragma unroll 8
        for (int k2 = 0; k2 < 64; k2++) {
            ull upz = bfpair(pz[k2 * 256]);
            ull upr = bfpair(pr[k2 * 256]);
            ulonglong2 hA = *(const ulonglong2*)(hpp + k2 * 4);
            ulonglong2 hB = *(const ulonglong2*)(hpp + k2 * 4 + 2);
            az[0] = fma2(upz, hA.x, az[0]);
            az[1] = fma2(upz, hA.y, az[1]);
            az[2] = fma2(upz, hB.x, az[2]);
            az[3] = fma2(upz, hB.y, az[3]);
            ar[0] = fma2(upr, hA.x, ar[0]);
            ar[1] = fma2(upr, hA.y, ar[1]);
            ar[2] = fma2(upr, hB.x, ar[2]);
            ar[3] = fma2(upr, hB.y, ar[3]);
        }
        if (g == 1) {
#pragma unroll
            for (int r = 0; r < BT; r++) {
                part[r * 256 + j]       = red2(az[r]);
                part[(4 + r) * 256 + j] = red2(ar[r]);
            }
        }
        __syncthreads();

        float zz[BT];
        if (g == 0) {
#pragma unroll
            for (int r = 0; r < BT; r++) {
                float sz = red2(az[r]) + part[r * 256 + j];
                float sr = red2(ar[r]) + part[(4 + r) * 256 + j];
                float z  = sigf(sz + fmaf(ev[r], wzw, wzb) + uzb);
                float rg = sigf(sr + fmaf(ev[r], wrw, wrb) + urb);
                zz[r] = z;
                rhp[pbase + r * 2] = rg * h_reg[r];
            }
        }
        __syncthreads();

        // ---- phase 2: h_tilde partial matvec over (r*h) ----
        ull ah[BT] = {0, 0, 0, 0};
#pragma unroll 8
        for (int k2 = 0; k2 < 64; k2++) {
            ull uph = bfpair(ph[k2 * 256]);
            ulonglong2 hA = *(const ulonglong2*)(rpp + k2 * 4);
            ulonglong2 hB = *(const ulonglong2*)(rpp + k2 * 4 + 2);
            ah[0] = fma2(uph, hA.x, ah[0]);
            ah[1] = fma2(uph, hA.y, ah[1]);
            ah[2] = fma2(uph, hB.x, ah[2]);
            ah[3] = fma2(uph, hB.y, ah[3]);
        }
        if (g == 1) {
#pragma unroll
            for (int r = 0; r < BT; r++) part[r * 256 + j] = red2(ah[r]);
        }
        __syncthreads();

        if (g == 0) {
#pragma unroll
            for (int r = 0; r < BT; r++) {
                float sh = red2(ah[r]) + part[r * 256 + j];
                float ht = tanhf_fast(sh + fmaf(ev[r], whw, whb) + uhb);
                float hh = (1.0f - zz[r]) * ht + zz[r] * h_reg[r];
                float gt = fmaf(gin[r], wgw, wgb);
                float hn = tanhf_fast(fmaf(gam, gt, hh));
                h_reg[r] = hn;
                hp[pbase + r * 2] = hn;
            }
        }
        __syncthreads();
    }

    // ---- epilogue: fc1 -> relu -> fc2 -> softplus -> vol ----
    float* h_lin = (float*)smem;          // reuse uz_sm region: [4][256]
    float* hid   = h_lin + BT * Hn;       // [4][256]
    if (g == 0) {
#pragma unroll
        for (int r = 0; r < BT; r++) h_lin[r * Hn + j] = h_reg[r];
    }
    __syncthreads();

    // fc1 split-k: this thread covers k in [g*128, g*128+128)
    {
        float acc[BT] = {0.f, 0.f, 0.f, 0.f};
        const int kb = g * 128;
        for (int k = kb; k < kb + 128; k++) {
            float f = fc1w[k * Hn + j];
#pragma unroll
            for (int r = 0; r < BT; r++) acc[r] = fmaf(h_lin[r * Hn + k], f, acc[r]);
        }
        if (g == 1) {
#pragma unroll
            for (int r = 0; r < BT; r++) part[r * 256 + j] = acc[r];
        }
        __syncthreads();
        if (g == 0) {
            float b1 = fc1b[j];
#pragma unroll
            for (int r = 0; r < BT; r++)
                hid[r * Hn + j] = fmaxf(acc[r] + part[r * 256 + j] + b1, 0.0f);
        }
        __syncthreads();
    }

    if (g == 0 && j < BT * HORn) {        // 88 threads
        int r = j / HORn;
        int o = j - r * HORn;
        float s = 0.0f;
        for (int k = 0; k < Hn; k++) s = fmaf(hid[r * Hn + k], fc2w[k * HORn + o], s);
        s += fc2b[o];
        float nn = (s > 20.0f) ? s : log1pf(expf(s));
        float vb = sqrtf(sigq[r] + 1e-8f);
        float vol = vb * (1.0f + nn);
        vol = fminf(fmaxf(vol, 0.01f), 10.0f);
        out[(r0 + r) * HORn + o] = vol;
    }
    if (g == 0 && j >= BT * HORn && j < BT * HORn + BT) {
        int r = j - BT * HORn;
        out[Bn * HORn + r0 + r] = sigq[r];
    }
}

extern "C" void kernel_launch(void* const* d_in, const int* in_sizes, int n_in,
                              void* d_out, int out_size) {
    const float* x    = (const float*)d_in[0];
    const float* Wzw  = (const float*)d_in[1];
    const float* Wzb  = (const float*)d_in[2];
    const float* Uzw  = (const float*)d_in[3];
    const float* Uzb  = (const float*)d_in[4];
    const float* Wrw  = (const float*)d_in[5];
    const float* Wrb  = (const float*)d_in[6];
    const float* Urw  = (const float*)d_in[7];
    const float* Urb  = (const float*)d_in[8];
    const float* Whw  = (const float*)d_in[9];
    const float* Whb  = (const float*)d_in[10];
    const float* Uhw  = (const float*)d_in[11];
    const float* Uhb  = (const float*)d_in[12];
    const float* Wgw  = (const float*)d_in[13];
    const float* Wgb  = (const float*)d_in[14];
    const float* om   = (const float*)d_in[15];
    const float* al   = (const float*)d_in[16];
    const float* be   = (const float*)d_in[17];
    const float* ga   = (const float*)d_in[18];
    const float* fc1w = (const float*)d_in[19];
    const float* fc1b = (const float*)d_in[20];
    const float* fc2w = (const float*)d_in[21];
    const float* fc2b = (const float*)d_in[22];
    float* out = (float*)d_out;

    ggru_pack_kernel<<<(3 * NK2 * Hn + 255) / 256, 256>>>(Uzw, Urw, Uhw);

    cudaFuncSetAttribute(ggru_main_kernel,
                         cudaFuncAttributeMaxDynamicSharedMemorySize, SMEM_BYTES);
    ggru_main_kernel<<<NCTA, NTHR, SMEM_BYTES>>>(
        x, Wzw, Wzb, Uzb, Wrw, Wrb, Urb, Whw, Whb, Uhb,
        Wgw, Wgb, om, al, be, ga, fc1w, fc1b, fc2w, fc2b, out);
}